// round 15
// baseline (speedup 1.0000x reference)
#include <cuda_runtime.h>
#include <cuda_fp16.h>
#include <cstdint>
#include <math.h>

#define NTOK 16384
#define HDIM 2048
#define FPN  1024
#define NCOLS 2050

#define BM 128
#define BN 128
#define BK 64
#define KIT (HDIM / BK)   // 32
#define STAGES 3

#define A_OFF 0
#define B_OFF 16384
#define STG   32768
#define SM_TOTAL (STAGES * STG)   // 98304 -> 2 CTAs/SM

// scratch (static device mem only; counters statically zeroed, reset by finalize)
__device__ float   g_logits[(size_t)NTOK * 1024];     // 64 MB
__device__ __half  g_Xh[(size_t)NTOK * HDIM];         // 64 MB
__device__ __half  g_Wh[(size_t)2 * FPN * HDIM];      // 8 MB
__device__ int     g_list[2][NTOK];
__device__ int     g_cnt[2] = {0, 0};
__device__ int     g_tile = 0;
__device__ float   g_endprob[NTOK];

__device__ __forceinline__ uint32_t smem_u32(const void* p) {
    uint32_t a;
    asm("{ .reg .u64 t; cvta.to.shared.u64 t, %1; cvt.u32.u64 %0, t; }" : "=r"(a) : "l"(p));
    return a;
}

#define CP16(dst, src) \
    asm volatile("cp.async.cg.shared.global [%0], [%1], 16;" :: "r"(dst), "l"(src))
#define CP_COMMIT() asm volatile("cp.async.commit_group;" ::: "memory")
#define CP_WAIT1()  asm volatile("cp.async.wait_group 1;" ::: "memory")

#define LDSM4(r, addr) \
    asm volatile("ldmatrix.sync.aligned.m8n8.x4.shared.b16 {%0,%1,%2,%3}, [%4];" \
        : "=r"((r)[0]), "=r"((r)[1]), "=r"((r)[2]), "=r"((r)[3]) : "r"(addr))

#define MMA_F16(c, a, b0, b1) \
    asm volatile("mma.sync.aligned.m16n8k16.row.col.f32.f16.f16.f32 " \
        "{%0,%1,%2,%3}, {%4,%5,%6,%7}, {%8,%9}, {%0,%1,%2,%3};" \
        : "+f"((c)[0]), "+f"((c)[1]), "+f"((c)[2]), "+f"((c)[3]) \
        : "r"((a)[0]), "r"((a)[1]), "r"((a)[2]), "r"((a)[3]), "r"(b0), "r"(b1))

// swizzled byte offset inside a 128-row x 128B tile (8 chunks/row, XOR by row&7)
__device__ __forceinline__ uint32_t swz(uint32_t row, uint32_t chunk) {
    return row * 128u + ((chunk ^ (row & 7u)) << 4);
}

__device__ __forceinline__ uint2 cvt4h(float4 v) {
    __half2 h01 = __floats2half2_rn(v.x, v.y);
    __half2 h23 = __floats2half2_rn(v.z, v.w);
    return make_uint2(*(uint32_t*)&h01, *(uint32_t*)&h23);
}

// ---------------- kernels ----------------
// blocks [0, 2048): per-warp classify + X fp16 convert + end-row output
// blocks [2048, 6144): W fp16 convert
__global__ void __launch_bounds__(256) prep_kernel(
    const float* __restrict__ X, const int* __restrict__ pY,
    const float* __restrict__ W_end, const float* __restrict__ b_end,
    const float* __restrict__ W0, const float* __restrict__ W1,
    float* __restrict__ out)
{
    if (blockIdx.x >= 2048) {
        int i = (blockIdx.x - 2048) * blockDim.x + threadIdx.x;
        const int half = FPN * HDIM / 4;
        const float4* src = (i < half) ? (const float4*)W0 + i
                                       : (const float4*)W1 + (i - half);
        reinterpret_cast<uint2*>(g_Wh)[i] = cvt4h(__ldcs(src));
        return;
    }
    int gwarp = (blockIdx.x * blockDim.x + threadIdx.x) >> 5;
    int lane  = threadIdx.x & 31;
    const float4* x = reinterpret_cast<const float4*>(X) + (size_t)gwarp * (HDIM / 4);
    const float4* w = reinterpret_cast<const float4*>(W_end);
    uint2* xh = reinterpret_cast<uint2*>(g_Xh + (size_t)gwarp * HDIM);
    int c = pY[gwarp];
    float acc = 0.f;
    if (c != 0) {
        #pragma unroll 4
        for (int i = lane; i < HDIM / 4; i += 32) {
            float4 a = __ldcs(x + i); float4 b = w[i];
            acc = fmaf(a.x, b.x, acc); acc = fmaf(a.y, b.y, acc);
            acc = fmaf(a.z, b.z, acc); acc = fmaf(a.w, b.w, acc);
            xh[i] = cvt4h(a);
        }
    } else {
        #pragma unroll 4
        for (int i = lane; i < HDIM / 4; i += 32) {
            float4 a = __ldcs(x + i); float4 b = w[i];
            acc = fmaf(a.x, b.x, acc); acc = fmaf(a.y, b.y, acc);
            acc = fmaf(a.z, b.z, acc); acc = fmaf(a.w, b.w, acc);
        }
    }
    #pragma unroll
    for (int o = 16; o > 0; o >>= 1) acc += __shfl_xor_sync(0xffffffffu, acc, o);
    acc = __shfl_sync(0xffffffffu, acc, 0);
    float logit = acc + b_end[0];
    float ep = 1.f / (1.f + expf(-logit));
    if (lane == 0) {
        g_endprob[gwarp] = ep;
        if (c == 1 || c == 2) {
            int pos = atomicAdd(&g_cnt[c - 1], 1);
            g_list[c - 1][pos] = gwarp;
        }
    }
    if (c == 0) {
        float* row = out + NTOK + (size_t)gwarp * NCOLS;
        float2* r2 = reinterpret_cast<float2*>(row + 2);   // 8B aligned (even idx)
        #pragma unroll 4
        for (int i = lane; i < 1024; i += 32) __stcs(r2 + i, make_float2(0.f, 0.f));
        if (lane == 0) {
            row[0] = ep; row[1] = ep;
            out[gwarp] = logf(ep);
        }
    }
}

// Persistent single-pass fp16 gathered GEMM (128x128, 2 CTAs/SM).
__global__ void __launch_bounds__(256, 2) gemm_mma_kernel(
    const float* __restrict__ b0, const float* __restrict__ b1)
{
    extern __shared__ char smem[];
    __shared__ int s_tile;
    uint32_t sb = smem_u32(smem);
    int tid = threadIdx.x;
    int lane = tid & 31, wid = tid >> 5;
    int wm = wid >> 2, wn = wid & 3;     // warp grid 2 x 4; warp tile 64 x 32

    int cnt0 = g_cnt[0], cnt1 = g_cnt[1];
    int tiles0 = (cnt0 + BM - 1) / BM, tiles1 = (cnt1 + BM - 1) / BM;
    int total = (tiles0 + tiles1) * 8;

    int c  = tid & 7;                    // 16B chunk 0..7 within 128B row
    int r0 = tid >> 3;                   // 0..31; rows r0 + j*32
    int sub = lane >> 3, r8 = lane & 7;
    int aRowL = (sub & 1) * 8 + r8, aChk = sub >> 1;
    int bRowL = (sub >> 1) * 8 + r8, bChk = sub & 1;

    const __half* pA[4];
    const __half* pB[4];
    uint32_t dOff[4];
    int selC, mtC, n0C, cntC;

    #define SETUP(t)                                                            \
        do {                                                                    \
            int u_;                                                             \
            if ((t) < tiles0 * 8) { selC = 0; u_ = (t);              cntC = cnt0; } \
            else                  { selC = 1; u_ = (t) - tiles0 * 8; cntC = cnt1; } \
            mtC = (u_ >> 3) * BM;                                               \
            n0C = (u_ & 7) * BN;                                                \
            const int* list_ = g_list[selC];                                    \
            _Pragma("unroll")                                                   \
            for (int j_ = 0; j_ < 4; j_++) {                                    \
                int r_ = r0 + j_ * 32;                                          \
                int m_ = mtC + r_;                                              \
                int tok_ = list_[m_ < cntC ? m_ : cntC - 1];                    \
                pA[j_] = g_Xh + (size_t)tok_ * HDIM + c * 8;                    \
                pB[j_] = g_Wh + (size_t)selC * FPN * HDIM                       \
                              + (size_t)(n0C + r_) * HDIM + c * 8;              \
                dOff[j_] = swz((uint32_t)r_, (uint32_t)c);                      \
            }                                                                   \
        } while (0)

    #define ISSUE_STAGE(stage, k0)                                              \
        do {                                                                    \
            uint32_t st_ = sb + (uint32_t)(stage) * STG;                        \
            _Pragma("unroll")                                                   \
            for (int j_ = 0; j_ < 4; j_++) {                                    \
                CP16(st_ + A_OFF + dOff[j_], pA[j_] + (k0));                    \
                CP16(st_ + B_OFF + dOff[j_], pB[j_] + (k0));                    \
            }                                                                   \
            CP_COMMIT();                                                        \
        } while (0)

    if (tid == 0) s_tile = atomicAdd(&g_tile, 1);
    __syncthreads();
    int t = s_tile;
    if (t >= total) return;
    SETUP(t);
    ISSUE_STAGE(0, 0);
    ISSUE_STAGE(1, BK);

    float acc[4][4][4];
    #pragma unroll
    for (int i = 0; i < 4; i++)
        #pragma unroll
        for (int j = 0; j < 4; j++)
            #pragma unroll
            for (int q = 0; q < 4; q++) acc[i][j][q] = 0.f;

    while (true) {
        for (int it = 0; it < KIT; it++) {
            CP_WAIT1();
            __syncthreads();
            int ld = it + STAGES - 1;
            if (ld < KIT) {
                ISSUE_STAGE(ld % STAGES, ld * BK);
            } else {
                CP_COMMIT();
            }
            uint32_t stOff = sb + (uint32_t)(it % STAGES) * STG;

            #pragma unroll
            for (int kk = 0; kk < 4; kk++) {
                uint32_t aF[4][4], bF[2][4];
                #pragma unroll
                for (int mt = 0; mt < 4; mt++) {
                    uint32_t r = (uint32_t)(wm * 64 + mt * 16 + aRowL);
                    LDSM4(aF[mt], stOff + A_OFF + swz(r, (uint32_t)(kk * 2 + aChk)));
                }
                #pragma unroll
                for (int p = 0; p < 2; p++) {
                    uint32_t r = (uint32_t)(wn * 32 + p * 16 + bRowL);
                    LDSM4(bF[p], stOff + B_OFF + swz(r, (uint32_t)(kk * 2 + bChk)));
                }
                #pragma unroll
                for (int mt = 0; mt < 4; mt++)
                    #pragma unroll
                    for (int nt = 0; nt < 4; nt++)
                        MMA_F16(acc[mt][nt], aF[mt],
                                bF[nt >> 1][(nt & 1) * 2], bF[nt >> 1][(nt & 1) * 2 + 1]);
            }
        }

        int selO = selC, mtO = mtC, n0O = n0C, cntO = cntC;
        if (tid == 0) s_tile = atomicAdd(&g_tile, 1);
        __syncthreads();
        int tn = s_tile;
        if (tn < total) {
            SETUP(tn);
            ISSUE_STAGE(0, 0);
            ISSUE_STAGE(1, BK);
        }

        // epilogue for old tile (overlaps next tile's loads)
        {
            const float* bias = selO ? b1 : b0;
            const int*   list = g_list[selO];
            int colB = wn * 32 + (lane & 3) * 2;
            float2 bv[4];
            #pragma unroll
            for (int nt = 0; nt < 4; nt++)
                bv[nt] = *(const float2*)(bias + n0O + colB + nt * 8);
            #pragma unroll
            for (int mt = 0; mt < 4; mt++) {
                int rr = mtO + wm * 64 + mt * 16 + (lane >> 2);
                #pragma unroll
                for (int h = 0; h < 2; h++) {
                    int row = rr + h * 8;
                    if (row < cntO) {
                        int tok = list[row];
                        float* dst = g_logits + (size_t)tok * 1024 + n0O + colB;
                        #pragma unroll
                        for (int nt = 0; nt < 4; nt++) {
                            float2 o;
                            o.x = acc[mt][nt][h * 2 + 0] + bv[nt].x;
                            o.y = acc[mt][nt][h * 2 + 1] + bv[nt].y;
                            *(float2*)(dst + nt * 8) = o;
                        }
                    }
                }
            }
        }

        t = tn;
        if (t >= total) break;
        #pragma unroll
        for (int i = 0; i < 4; i++)
            #pragma unroll
            for (int j = 0; j < 4; j++)
                #pragma unroll
                for (int q = 0; q < 4; q++) acc[i][j][q] = 0.f;
    }
    #undef ISSUE_STAGE
    #undef SETUP
}

// one WARP per token: softmax + row write, no __syncthreads; counters reset here
__global__ void __launch_bounds__(256) finalize_kernel(
    const int* __restrict__ pY, const int* __restrict__ Y,
    float* __restrict__ out)
{
    int tid = threadIdx.x;
    int wid = tid >> 5, lane = tid & 31;
    if (blockIdx.x == 0 && tid < 3) {
        if (tid < 2) g_cnt[tid] = 0; else g_tile = 0;
    }
    int n = blockIdx.x * 8 + wid;
    int cls = pY[n];
    if (cls == 0) return;
    float ep = g_endprob[n];
    float* row = out + NTOK + (size_t)n * NCOLS;

    const float4* lg4 = reinterpret_cast<const float4*>(g_logits + (size_t)n * 1024);
    float4 q[8], e[8];
    float s = 0.f;
    #pragma unroll
    for (int j = 0; j < 8; j++) {
        q[j] = lg4[lane + j * 32];
        e[j].x = __expf(q[j].x); e[j].y = __expf(q[j].y);
        e[j].z = __expf(q[j].z); e[j].w = __expf(q[j].w);
        s += (e[j].x + e[j].y) + (e[j].z + e[j].w);
    }
    #pragma unroll
    for (int o = 16; o > 0; o >>= 1) s += __shfl_xor_sync(0xffffffffu, s, o);

    float nonend = 1.f - ep;
    float scale = nonend / s;
    int off  = (cls == 1) ? 2 : (2 + FPN);
    int zoff = (cls == 1) ? (2 + FPN) : 2;
    float2* po = reinterpret_cast<float2*>(row + off);
    float2* pz = reinterpret_cast<float2*>(row + zoff);
    #pragma unroll
    for (int j = 0; j < 8; j++) {
        int cb = (lane + j * 32) * 2;   // float2 index
        __stcs(po + cb + 0, make_float2(e[j].x * scale, e[j].y * scale));
        __stcs(po + cb + 1, make_float2(e[j].z * scale, e[j].w * scale));
        __stcs(pz + cb + 0, make_float2(0.f, 0.f));
        __stcs(pz + cb + 1, make_float2(0.f, 0.f));
    }
    if (lane == 0) { row[0] = 0.f; row[1] = 0.f; }

    int idx = Y[n] - 2 - ((cls == 2) ? FPN : 0);
    idx = min(max(idx, 0), 1023);
    int g = idx >> 2;                    // float4 group
    if (lane == (g & 31)) {
        int j = g >> 5;
        float v = (idx & 2) ? ((idx & 1) ? q[j].w : q[j].z)
                            : ((idx & 1) ? q[j].y : q[j].x);
        out[n] = (v - logf(s)) + logf(nonend);
    }
}

extern "C" void kernel_launch(void* const* d_in, const int* in_sizes, int n_in,
                              void* d_out, int out_size)
{
    const float* X     = (const float*)d_in[0];
    const int*   pY    = (const int*)  d_in[1];
    const int*   Y     = (const int*)  d_in[2];
    const float* W_end = (const float*)d_in[3];
    const float* b_end = (const float*)d_in[4];
    const float* W_hcw = (const float*)d_in[5];
    const float* b_hcw = (const float*)d_in[6];
    const float* W_roo = (const float*)d_in[7];
    const float* b_roo = (const float*)d_in[8];
    float* out = (float*)d_out;

    cudaFuncSetAttribute(gemm_mma_kernel,
                         cudaFuncAttributeMaxDynamicSharedMemorySize, SM_TOTAL);

    prep_kernel<<<2048 + 4096, 256>>>(X, pY, W_end, b_end, W_hcw, W_roo, out);
    gemm_mma_kernel<<<304, 256, SM_TOTAL>>>(b_hcw, b_roo);   // persistent, 2 CTAs/SM
    finalize_kernel<<<NTOK / 8, 256>>>(pY, Y, out);
}

// round 16
// speedup vs baseline: 1.0311x; 1.0311x over previous
#include <cuda_runtime.h>
#include <cuda_fp16.h>
#include <cstdint>
#include <math.h>

#define NTOK 16384
#define HDIM 2048
#define FPN  1024
#define NCOLS 2050

#define BM 128
#define BN 128
#define BK 64
#define KIT (HDIM / BK)   // 32
#define STAGES 3

#define A_OFF 0
#define B_OFF 16384
#define STG   32768
#define SM_TOTAL (STAGES * STG)   // 98304 -> 2 CTAs/SM

// scratch (static device mem only; counters statically zeroed, reset by finalize)
__device__ float   g_logits[(size_t)NTOK * 1024];     // 64 MB
__device__ __half  g_Xh[(size_t)NTOK * HDIM];         // 64 MB
__device__ __half  g_Wh[(size_t)2 * FPN * HDIM];      // 8 MB
__device__ int     g_list[2][NTOK];
__device__ int     g_cnt[2] = {0, 0};
__device__ int     g_tile = 0;
__device__ float   g_endprob[NTOK];

__device__ __forceinline__ uint32_t smem_u32(const void* p) {
    uint32_t a;
    asm("{ .reg .u64 t; cvta.to.shared.u64 t, %1; cvt.u32.u64 %0, t; }" : "=r"(a) : "l"(p));
    return a;
}

#define CP16(dst, src) \
    asm volatile("cp.async.cg.shared.global [%0], [%1], 16;" :: "r"(dst), "l"(src))
#define CP_COMMIT() asm volatile("cp.async.commit_group;" ::: "memory")
#define CP_WAIT1()  asm volatile("cp.async.wait_group 1;" ::: "memory")

#define LDSM4(r, addr) \
    asm volatile("ldmatrix.sync.aligned.m8n8.x4.shared.b16 {%0,%1,%2,%3}, [%4];" \
        : "=r"((r)[0]), "=r"((r)[1]), "=r"((r)[2]), "=r"((r)[3]) : "r"(addr))

#define MMA_F16(c, a, b0, b1) \
    asm volatile("mma.sync.aligned.m16n8k16.row.col.f32.f16.f16.f32 " \
        "{%0,%1,%2,%3}, {%4,%5,%6,%7}, {%8,%9}, {%0,%1,%2,%3};" \
        : "+f"((c)[0]), "+f"((c)[1]), "+f"((c)[2]), "+f"((c)[3]) \
        : "r"((a)[0]), "r"((a)[1]), "r"((a)[2]), "r"((a)[3]), "r"(b0), "r"(b1))

// swizzled byte offset inside a 128-row x 128B tile (8 chunks/row, XOR by row&7)
__device__ __forceinline__ uint32_t swz(uint32_t row, uint32_t chunk) {
    return row * 128u + ((chunk ^ (row & 7u)) << 4);
}

__device__ __forceinline__ uint2 cvt4h(float4 v) {
    __half2 h01 = __floats2half2_rn(v.x, v.y);
    __half2 h23 = __floats2half2_rn(v.z, v.w);
    return make_uint2(*(uint32_t*)&h01, *(uint32_t*)&h23);
}

// ---------------- kernels ----------------
// blocks [0, 2048): per-warp classify + X fp16 convert + end-row output
// blocks [2048, 6144): W fp16 convert
__global__ void __launch_bounds__(256) prep_kernel(
    const float* __restrict__ X, const int* __restrict__ pY,
    const float* __restrict__ W_end, const float* __restrict__ b_end,
    const float* __restrict__ W0, const float* __restrict__ W1,
    float* __restrict__ out)
{
    if (blockIdx.x >= 2048) {
        int i = (blockIdx.x - 2048) * blockDim.x + threadIdx.x;
        const int half = FPN * HDIM / 4;
        const float4* src = (i < half) ? (const float4*)W0 + i
                                       : (const float4*)W1 + (i - half);
        reinterpret_cast<uint2*>(g_Wh)[i] = cvt4h(*src);
        return;
    }
    int gwarp = (blockIdx.x * blockDim.x + threadIdx.x) >> 5;
    int lane  = threadIdx.x & 31;
    const float4* x = reinterpret_cast<const float4*>(X) + (size_t)gwarp * (HDIM / 4);
    const float4* w = reinterpret_cast<const float4*>(W_end);
    uint2* xh = reinterpret_cast<uint2*>(g_Xh + (size_t)gwarp * HDIM);
    int c = pY[gwarp];
    float acc = 0.f;
    if (c != 0) {
        #pragma unroll 4
        for (int i = lane; i < HDIM / 4; i += 32) {
            float4 a = x[i]; float4 b = w[i];
            acc = fmaf(a.x, b.x, acc); acc = fmaf(a.y, b.y, acc);
            acc = fmaf(a.z, b.z, acc); acc = fmaf(a.w, b.w, acc);
            xh[i] = cvt4h(a);
        }
    } else {
        #pragma unroll 4
        for (int i = lane; i < HDIM / 4; i += 32) {
            float4 a = x[i]; float4 b = w[i];
            acc = fmaf(a.x, b.x, acc); acc = fmaf(a.y, b.y, acc);
            acc = fmaf(a.z, b.z, acc); acc = fmaf(a.w, b.w, acc);
        }
    }
    #pragma unroll
    for (int o = 16; o > 0; o >>= 1) acc += __shfl_xor_sync(0xffffffffu, acc, o);
    acc = __shfl_sync(0xffffffffu, acc, 0);
    float logit = acc + b_end[0];
    float ep = 1.f / (1.f + expf(-logit));
    if (lane == 0) {
        g_endprob[gwarp] = ep;
        if (c == 1 || c == 2) {
            int pos = atomicAdd(&g_cnt[c - 1], 1);
            g_list[c - 1][pos] = gwarp;
        }
    }
    if (c == 0) {
        float* row = out + NTOK + (size_t)gwarp * NCOLS;
        float2* r2 = reinterpret_cast<float2*>(row + 2);   // 8B aligned (even idx)
        #pragma unroll 4
        for (int i = lane; i < 1024; i += 32) __stcs(r2 + i, make_float2(0.f, 0.f));
        if (lane == 0) {
            row[0] = ep; row[1] = ep;
            out[gwarp] = logf(ep);
        }
    }
}

// Persistent single-pass fp16 gathered GEMM (128x128, 2 CTAs/SM).
__global__ void __launch_bounds__(256, 2) gemm_mma_kernel(
    const float* __restrict__ b0, const float* __restrict__ b1)
{
    extern __shared__ char smem[];
    __shared__ int s_tile;
    uint32_t sb = smem_u32(smem);
    int tid = threadIdx.x;
    int lane = tid & 31, wid = tid >> 5;
    int wm = wid >> 2, wn = wid & 3;     // warp grid 2 x 4; warp tile 64 x 32

    int cnt0 = g_cnt[0], cnt1 = g_cnt[1];
    int tiles0 = (cnt0 + BM - 1) / BM, tiles1 = (cnt1 + BM - 1) / BM;
    int total = (tiles0 + tiles1) * 8;

    int c  = tid & 7;                    // 16B chunk 0..7 within 128B row
    int r0 = tid >> 3;                   // 0..31; rows r0 + j*32
    int sub = lane >> 3, r8 = lane & 7;
    int aRowL = (sub & 1) * 8 + r8, aChk = sub >> 1;
    int bRowL = (sub >> 1) * 8 + r8, bChk = sub & 1;

    const __half* pA[4];
    const __half* pB[4];
    uint32_t dOff[4];
    int selC, mtC, n0C, cntC;

    #define SETUP(t)                                                            \
        do {                                                                    \
            int u_;                                                             \
            if ((t) < tiles0 * 8) { selC = 0; u_ = (t);              cntC = cnt0; } \
            else                  { selC = 1; u_ = (t) - tiles0 * 8; cntC = cnt1; } \
            mtC = (u_ >> 3) * BM;                                               \
            n0C = (u_ & 7) * BN;                                                \
            const int* list_ = g_list[selC];                                    \
            _Pragma("unroll")                                                   \
            for (int j_ = 0; j_ < 4; j_++) {                                    \
                int r_ = r0 + j_ * 32;                                          \
                int m_ = mtC + r_;                                              \
                int tok_ = list_[m_ < cntC ? m_ : cntC - 1];                    \
                pA[j_] = g_Xh + (size_t)tok_ * HDIM + c * 8;                    \
                pB[j_] = g_Wh + (size_t)selC * FPN * HDIM                       \
                              + (size_t)(n0C + r_) * HDIM + c * 8;              \
                dOff[j_] = swz((uint32_t)r_, (uint32_t)c);                      \
            }                                                                   \
        } while (0)

    #define ISSUE_STAGE(stage, k0)                                              \
        do {                                                                    \
            uint32_t st_ = sb + (uint32_t)(stage) * STG;                        \
            _Pragma("unroll")                                                   \
            for (int j_ = 0; j_ < 4; j_++) {                                    \
                CP16(st_ + A_OFF + dOff[j_], pA[j_] + (k0));                    \
                CP16(st_ + B_OFF + dOff[j_], pB[j_] + (k0));                    \
            }                                                                   \
            CP_COMMIT();                                                        \
        } while (0)

    if (tid == 0) s_tile = atomicAdd(&g_tile, 1);
    __syncthreads();
    int t = s_tile;
    if (t >= total) return;
    SETUP(t);
    ISSUE_STAGE(0, 0);
    ISSUE_STAGE(1, BK);

    float acc[4][4][4];
    #pragma unroll
    for (int i = 0; i < 4; i++)
        #pragma unroll
        for (int j = 0; j < 4; j++)
            #pragma unroll
            for (int q = 0; q < 4; q++) acc[i][j][q] = 0.f;

    while (true) {
        for (int it = 0; it < KIT; it++) {
            CP_WAIT1();
            __syncthreads();
            int ld = it + STAGES - 1;
            if (ld < KIT) {
                ISSUE_STAGE(ld % STAGES, ld * BK);
            } else {
                CP_COMMIT();
            }
            uint32_t stOff = sb + (uint32_t)(it % STAGES) * STG;

            #pragma unroll
            for (int kk = 0; kk < 4; kk++) {
                uint32_t aF[4][4], bF[2][4];
                #pragma unroll
                for (int mt = 0; mt < 4; mt++) {
                    uint32_t r = (uint32_t)(wm * 64 + mt * 16 + aRowL);
                    LDSM4(aF[mt], stOff + A_OFF + swz(r, (uint32_t)(kk * 2 + aChk)));
                }
                #pragma unroll
                for (int p = 0; p < 2; p++) {
                    uint32_t r = (uint32_t)(wn * 32 + p * 16 + bRowL);
                    LDSM4(bF[p], stOff + B_OFF + swz(r, (uint32_t)(kk * 2 + bChk)));
                }
                #pragma unroll
                for (int mt = 0; mt < 4; mt++)
                    #pragma unroll
                    for (int nt = 0; nt < 4; nt++)
                        MMA_F16(acc[mt][nt], aF[mt],
                                bF[nt >> 1][(nt & 1) * 2], bF[nt >> 1][(nt & 1) * 2 + 1]);
            }
        }

        int selO = selC, mtO = mtC, n0O = n0C, cntO = cntC;
        if (tid == 0) s_tile = atomicAdd(&g_tile, 1);
        __syncthreads();
        int tn = s_tile;
        if (tn < total) {
            SETUP(tn);
            ISSUE_STAGE(0, 0);
            ISSUE_STAGE(1, BK);
        }

        // epilogue for old tile (overlaps next tile's loads)
        {
            const float* bias = selO ? b1 : b0;
            const int*   list = g_list[selO];
            int colB = wn * 32 + (lane & 3) * 2;
            float2 bv[4];
            #pragma unroll
            for (int nt = 0; nt < 4; nt++)
                bv[nt] = *(const float2*)(bias + n0O + colB + nt * 8);
            #pragma unroll
            for (int mt = 0; mt < 4; mt++) {
                int rr = mtO + wm * 64 + mt * 16 + (lane >> 2);
                #pragma unroll
                for (int h = 0; h < 2; h++) {
                    int row = rr + h * 8;
                    if (row < cntO) {
                        int tok = list[row];
                        float* dst = g_logits + (size_t)tok * 1024 + n0O + colB;
                        #pragma unroll
                        for (int nt = 0; nt < 4; nt++) {
                            float2 o;
                            o.x = acc[mt][nt][h * 2 + 0] + bv[nt].x;
                            o.y = acc[mt][nt][h * 2 + 1] + bv[nt].y;
                            *(float2*)(dst + nt * 8) = o;
                        }
                    }
                }
            }
        }

        t = tn;
        if (t >= total) break;
        #pragma unroll
        for (int i = 0; i < 4; i++)
            #pragma unroll
            for (int j = 0; j < 4; j++)
                #pragma unroll
                for (int q = 0; q < 4; q++) acc[i][j][q] = 0.f;
    }
    #undef ISSUE_STAGE
    #undef SETUP
}

// one WARP per token: softmax + row write, no __syncthreads; counters reset here
__global__ void __launch_bounds__(256) finalize_kernel(
    const int* __restrict__ pY, const int* __restrict__ Y,
    float* __restrict__ out)
{
    int tid = threadIdx.x;
    int wid = tid >> 5, lane = tid & 31;
    if (blockIdx.x == 0 && tid < 3) {
        if (tid < 2) g_cnt[tid] = 0; else g_tile = 0;
    }
    int n = blockIdx.x * 8 + wid;
    int cls = pY[n];
    if (cls == 0) return;
    float ep = g_endprob[n];
    float* row = out + NTOK + (size_t)n * NCOLS;

    const float4* lg4 = reinterpret_cast<const float4*>(g_logits + (size_t)n * 1024);
    float4 q[8], e[8];
    float s = 0.f;
    #pragma unroll
    for (int j = 0; j < 8; j++) {
        q[j] = lg4[lane + j * 32];
        e[j].x = __expf(q[j].x); e[j].y = __expf(q[j].y);
        e[j].z = __expf(q[j].z); e[j].w = __expf(q[j].w);
        s += (e[j].x + e[j].y) + (e[j].z + e[j].w);
    }
    #pragma unroll
    for (int o = 16; o > 0; o >>= 1) s += __shfl_xor_sync(0xffffffffu, s, o);

    float nonend = 1.f - ep;
    float scale = nonend / s;
    int off  = (cls == 1) ? 2 : (2 + FPN);
    int zoff = (cls == 1) ? (2 + FPN) : 2;
    float2* po = reinterpret_cast<float2*>(row + off);
    float2* pz = reinterpret_cast<float2*>(row + zoff);
    #pragma unroll
    for (int j = 0; j < 8; j++) {
        int cb = (lane + j * 32) * 2;   // float2 index
        __stcs(po + cb + 0, make_float2(e[j].x * scale, e[j].y * scale));
        __stcs(po + cb + 1, make_float2(e[j].z * scale, e[j].w * scale));
        __stcs(pz + cb + 0, make_float2(0.f, 0.f));
        __stcs(pz + cb + 1, make_float2(0.f, 0.f));
    }
    if (lane == 0) { row[0] = 0.f; row[1] = 0.f; }

    int idx = Y[n] - 2 - ((cls == 2) ? FPN : 0);
    idx = min(max(idx, 0), 1023);
    int g = idx >> 2;                    // float4 group
    if (lane == (g & 31)) {
        int j = g >> 5;
        float v = (idx & 2) ? ((idx & 1) ? q[j].w : q[j].z)
                            : ((idx & 1) ? q[j].y : q[j].x);
        out[n] = (v - logf(s)) + logf(nonend);
    }
}

extern "C" void kernel_launch(void* const* d_in, const int* in_sizes, int n_in,
                              void* d_out, int out_size)
{
    const float* X     = (const float*)d_in[0];
    const int*   pY    = (const int*)  d_in[1];
    const int*   Y     = (const int*)  d_in[2];
    const float* W_end = (const float*)d_in[3];
    const float* b_end = (const float*)d_in[4];
    const float* W_hcw = (const float*)d_in[5];
    const float* b_hcw = (const float*)d_in[6];
    const float* W_roo = (const float*)d_in[7];
    const float* b_roo = (const float*)d_in[8];
    float* out = (float*)d_out;

    cudaFuncSetAttribute(gemm_mma_kernel,
                         cudaFuncAttributeMaxDynamicSharedMemorySize, SM_TOTAL);

    prep_kernel<<<2048 + 4096, 256>>>(X, pY, W_end, b_end, W_hcw, W_roo, out);
    gemm_mma_kernel<<<304, 256, SM_TOTAL>>>(b_hcw, b_roo);   // persistent, 2 CTAs/SM
    finalize_kernel<<<NTOK / 8, 256>>>(pY, Y, out);
}

// round 17
// speedup vs baseline: 1.0483x; 1.0166x over previous
#include <cuda_runtime.h>
#include <cuda_fp16.h>
#include <cstdint>
#include <math.h>

#define NTOK 16384
#define HDIM 2048
#define FPN  1024
#define NCOLS 2050

#define BM 128
#define BN 128
#define BK 64
#define KIT (HDIM / BK)   // 32
#define STAGES 3

#define A_OFF 0
#define B_OFF 16384
#define STG   32768
#define SM_TOTAL (STAGES * STG)   // 98304 -> 2 CTAs/SM

// scratch (static device mem only; counters statically zeroed, reset by finalize)
__device__ float   g_logits[(size_t)NTOK * 1024];     // 64 MB
__device__ __half  g_Xh[(size_t)NTOK * HDIM];         // 64 MB
__device__ __half  g_Wh[(size_t)2 * FPN * HDIM];      // 8 MB
__device__ int     g_list[2][NTOK];
__device__ int     g_cnt[2] = {0, 0};
__device__ int     g_tile = 0;
__device__ float   g_endprob[NTOK];

__device__ __forceinline__ uint32_t smem_u32(const void* p) {
    uint32_t a;
    asm("{ .reg .u64 t; cvta.to.shared.u64 t, %1; cvt.u32.u64 %0, t; }" : "=r"(a) : "l"(p));
    return a;
}

#define CP16(dst, src) \
    asm volatile("cp.async.cg.shared.global [%0], [%1], 16;" :: "r"(dst), "l"(src))
#define CP_COMMIT() asm volatile("cp.async.commit_group;" ::: "memory")
#define CP_WAIT1()  asm volatile("cp.async.wait_group 1;" ::: "memory")

#define LDSM4(r, addr) \
    asm volatile("ldmatrix.sync.aligned.m8n8.x4.shared.b16 {%0,%1,%2,%3}, [%4];" \
        : "=r"((r)[0]), "=r"((r)[1]), "=r"((r)[2]), "=r"((r)[3]) : "r"(addr))

#define MMA_F16(c, a, b0, b1) \
    asm volatile("mma.sync.aligned.m16n8k16.row.col.f32.f16.f16.f32 " \
        "{%0,%1,%2,%3}, {%4,%5,%6,%7}, {%8,%9}, {%0,%1,%2,%3};" \
        : "+f"((c)[0]), "+f"((c)[1]), "+f"((c)[2]), "+f"((c)[3]) \
        : "r"((a)[0]), "r"((a)[1]), "r"((a)[2]), "r"((a)[3]), "r"(b0), "r"(b1))

// swizzled byte offset inside a 128-row x 128B tile (8 chunks/row, XOR by row&7)
__device__ __forceinline__ uint32_t swz(uint32_t row, uint32_t chunk) {
    return row * 128u + ((chunk ^ (row & 7u)) << 4);
}

__device__ __forceinline__ uint2 cvt4h(float4 v) {
    __half2 h01 = __floats2half2_rn(v.x, v.y);
    __half2 h23 = __floats2half2_rn(v.z, v.w);
    return make_uint2(*(uint32_t*)&h01, *(uint32_t*)&h23);
}

// ---------------- kernels ----------------
// blocks [0, 2048): per-warp classify + X fp16 convert + end-row output
// blocks [2048, 6144): W fp16 convert
__global__ void __launch_bounds__(256) prep_kernel(
    const float* __restrict__ X, const int* __restrict__ pY,
    const float* __restrict__ W_end, const float* __restrict__ b_end,
    const float* __restrict__ W0, const float* __restrict__ W1,
    float* __restrict__ out)
{
    if (blockIdx.x >= 2048) {
        int i = (blockIdx.x - 2048) * blockDim.x + threadIdx.x;
        const int half = FPN * HDIM / 4;
        const float4* src = (i < half) ? (const float4*)W0 + i
                                       : (const float4*)W1 + (i - half);
        reinterpret_cast<uint2*>(g_Wh)[i] = cvt4h(*src);
        return;
    }
    int gwarp = (blockIdx.x * blockDim.x + threadIdx.x) >> 5;
    int lane  = threadIdx.x & 31;
    const float4* x = reinterpret_cast<const float4*>(X) + (size_t)gwarp * (HDIM / 4);
    const float4* w = reinterpret_cast<const float4*>(W_end);
    uint2* xh = reinterpret_cast<uint2*>(g_Xh + (size_t)gwarp * HDIM);
    int c = pY[gwarp];
    float acc = 0.f;
    if (c != 0) {
        #pragma unroll 4
        for (int i = lane; i < HDIM / 4; i += 32) {
            float4 a = x[i]; float4 b = w[i];
            acc = fmaf(a.x, b.x, acc); acc = fmaf(a.y, b.y, acc);
            acc = fmaf(a.z, b.z, acc); acc = fmaf(a.w, b.w, acc);
            xh[i] = cvt4h(a);
        }
    } else {
        #pragma unroll 4
        for (int i = lane; i < HDIM / 4; i += 32) {
            float4 a = x[i]; float4 b = w[i];
            acc = fmaf(a.x, b.x, acc); acc = fmaf(a.y, b.y, acc);
            acc = fmaf(a.z, b.z, acc); acc = fmaf(a.w, b.w, acc);
        }
    }
    #pragma unroll
    for (int o = 16; o > 0; o >>= 1) acc += __shfl_xor_sync(0xffffffffu, acc, o);
    acc = __shfl_sync(0xffffffffu, acc, 0);
    float logit = acc + b_end[0];
    float ep = 1.f / (1.f + expf(-logit));
    if (lane == 0) {
        g_endprob[gwarp] = ep;
        if (c == 1 || c == 2) {
            int pos = atomicAdd(&g_cnt[c - 1], 1);
            g_list[c - 1][pos] = gwarp;
        }
    }
    if (c == 0) {
        float* row = out + NTOK + (size_t)gwarp * NCOLS;
        float2* r2 = reinterpret_cast<float2*>(row + 2);   // 8B aligned (even idx)
        #pragma unroll 4
        for (int i = lane; i < 1024; i += 32) __stcs(r2 + i, make_float2(0.f, 0.f));
        if (lane == 0) {
            row[0] = ep; row[1] = ep;
            out[gwarp] = logf(ep);
        }
    }
}

// Persistent single-pass fp16 gathered GEMM.
// CTA tile 128x128, 4 warps (grid 2x2), warp tile 64x64, 2 CTAs/SM.
__global__ void __launch_bounds__(128, 2) gemm_mma_kernel(
    const float* __restrict__ b0, const float* __restrict__ b1)
{
    extern __shared__ char smem[];
    __shared__ int s_tile;
    uint32_t sb = smem_u32(smem);
    int tid = threadIdx.x;
    int lane = tid & 31, wid = tid >> 5;
    int wm = wid >> 1, wn = wid & 1;     // warp grid 2 x 2; warp tile 64 x 64

    int cnt0 = g_cnt[0], cnt1 = g_cnt[1];
    int tiles0 = (cnt0 + BM - 1) / BM, tiles1 = (cnt1 + BM - 1) / BM;
    int total = (tiles0 + tiles1) * 8;

    int c  = tid & 7;                    // 16B chunk 0..7 within 128B row
    int r0 = tid >> 3;                   // 0..15; rows r0 + j*16
    int sub = lane >> 3, r8 = lane & 7;
    int aRowL = (sub & 1) * 8 + r8, aChk = sub >> 1;
    int bRowL = (sub >> 1) * 8 + r8, bChk = sub & 1;

    const __half* pA[8];                 // gathered token rows r0 + j*16
    const __half* pB0;                   // W row (n0 + r0); + j*16*HDIM
    uint32_t dOff0;
    int selC, mtC, n0C, cntC;

    #define SETUP(t)                                                            \
        do {                                                                    \
            int u_;                                                             \
            if ((t) < tiles0 * 8) { selC = 0; u_ = (t);              cntC = cnt0; } \
            else                  { selC = 1; u_ = (t) - tiles0 * 8; cntC = cnt1; } \
            mtC = (u_ >> 3) * BM;                                               \
            n0C = (u_ & 7) * BN;                                                \
            const int* list_ = g_list[selC];                                    \
            _Pragma("unroll")                                                   \
            for (int j_ = 0; j_ < 8; j_++) {                                    \
                int m_ = mtC + r0 + j_ * 16;                                    \
                int tok_ = list_[m_ < cntC ? m_ : cntC - 1];                    \
                pA[j_] = g_Xh + (size_t)tok_ * HDIM + c * 8;                    \
            }                                                                   \
            pB0 = g_Wh + (size_t)selC * FPN * HDIM                              \
                       + (size_t)(n0C + r0) * HDIM + c * 8;                     \
            dOff0 = swz((uint32_t)r0, (uint32_t)c);                             \
        } while (0)

    // rows r0 + j*16: (r&7) invariant mod 16 -> dOff(j) = dOff0 + j*16*128
    #define ISSUE_STAGE(stage, k0)                                              \
        do {                                                                    \
            uint32_t st_ = sb + (uint32_t)(stage) * STG;                        \
            _Pragma("unroll")                                                   \
            for (int j_ = 0; j_ < 8; j_++) {                                    \
                uint32_t d_ = dOff0 + (uint32_t)(j_ * 2048);                    \
                CP16(st_ + A_OFF + d_, pA[j_] + (k0));                          \
                CP16(st_ + B_OFF + d_, pB0 + (size_t)j_ * 16 * HDIM + (k0));    \
            }                                                                   \
            CP_COMMIT();                                                        \
        } while (0)

    if (tid == 0) s_tile = atomicAdd(&g_tile, 1);
    __syncthreads();
    int t = s_tile;
    if (t >= total) return;
    SETUP(t);
    ISSUE_STAGE(0, 0);
    ISSUE_STAGE(1, BK);

    float acc[4][8][4];
    #pragma unroll
    for (int i = 0; i < 4; i++)
        #pragma unroll
        for (int j = 0; j < 8; j++)
            #pragma unroll
            for (int q = 0; q < 4; q++) acc[i][j][q] = 0.f;

    while (true) {
        for (int it = 0; it < KIT; it++) {
            CP_WAIT1();
            __syncthreads();
            int ld = it + STAGES - 1;
            if (ld < KIT) {
                ISSUE_STAGE(ld % STAGES, ld * BK);
            } else {
                CP_COMMIT();
            }
            uint32_t stOff = sb + (uint32_t)(it % STAGES) * STG;

            #pragma unroll
            for (int kk = 0; kk < 4; kk++) {
                uint32_t aF[4][4], bF[4][4];
                #pragma unroll
                for (int mt = 0; mt < 4; mt++) {
                    uint32_t r = (uint32_t)(wm * 64 + mt * 16 + aRowL);
                    LDSM4(aF[mt], stOff + A_OFF + swz(r, (uint32_t)(kk * 2 + aChk)));
                }
                #pragma unroll
                for (int p = 0; p < 4; p++) {
                    uint32_t r = (uint32_t)(wn * 64 + p * 16 + bRowL);
                    LDSM4(bF[p], stOff + B_OFF + swz(r, (uint32_t)(kk * 2 + bChk)));
                }
                #pragma unroll
                for (int mt = 0; mt < 4; mt++)
                    #pragma unroll
                    for (int nt = 0; nt < 8; nt++)
                        MMA_F16(acc[mt][nt], aF[mt],
                                bF[nt >> 1][(nt & 1) * 2], bF[nt >> 1][(nt & 1) * 2 + 1]);
            }
        }

        int selO = selC, mtO = mtC, n0O = n0C, cntO = cntC;
        if (tid == 0) s_tile = atomicAdd(&g_tile, 1);
        __syncthreads();
        int tn = s_tile;
        if (tn < total) {
            SETUP(tn);
            ISSUE_STAGE(0, 0);
            ISSUE_STAGE(1, BK);
        }

        // epilogue for old tile (overlaps next tile's loads)
        {
            const float* bias = selO ? b1 : b0;
            const int*   list = g_list[selO];
            int colB = wn * 64 + (lane & 3) * 2;
            float2 bv[8];
            #pragma unroll
            for (int nt = 0; nt < 8; nt++)
                bv[nt] = *(const float2*)(bias + n0O + colB + nt * 8);
            #pragma unroll
            for (int mt = 0; mt < 4; mt++) {
                int rr = mtO + wm * 64 + mt * 16 + (lane >> 2);
                #pragma unroll
                for (int h = 0; h < 2; h++) {
                    int row = rr + h * 8;
                    if (row < cntO) {
                        int tok = list[row];
                        float* dst = g_logits + (size_t)tok * 1024 + n0O + colB;
                        #pragma unroll
                        for (int nt = 0; nt < 8; nt++) {
                            float2 o;
                            o.x = acc[mt][nt][h * 2 + 0] + bv[nt].x;
                            o.y = acc[mt][nt][h * 2 + 1] + bv[nt].y;
                            *(float2*)(dst + nt * 8) = o;
                        }
                    }
                }
            }
        }

        t = tn;
        if (t >= total) break;
        #pragma unroll
        for (int i = 0; i < 4; i++)
            #pragma unroll
            for (int j = 0; j < 8; j++)
                #pragma unroll
                for (int q = 0; q < 4; q++) acc[i][j][q] = 0.f;
    }
    #undef ISSUE_STAGE
    #undef SETUP
}

// one WARP per token: softmax + row write, no __syncthreads; counters reset here
__global__ void __launch_bounds__(256) finalize_kernel(
    const int* __restrict__ pY, const int* __restrict__ Y,
    float* __restrict__ out)
{
    int tid = threadIdx.x;
    int wid = tid >> 5, lane = tid & 31;
    if (blockIdx.x == 0 && tid < 3) {
        if (tid < 2) g_cnt[tid] = 0; else g_tile = 0;
    }
    int n = blockIdx.x * 8 + wid;
    int cls = pY[n];
    if (cls == 0) return;
    float ep = g_endprob[n];
    float* row = out + NTOK + (size_t)n * NCOLS;

    const float4* lg4 = reinterpret_cast<const float4*>(g_logits + (size_t)n * 1024);
    float4 q[8], e[8];
    float s = 0.f;
    #pragma unroll
    for (int j = 0; j < 8; j++) {
        q[j] = lg4[lane + j * 32];
        e[j].x = __expf(q[j].x); e[j].y = __expf(q[j].y);
        e[j].z = __expf(q[j].z); e[j].w = __expf(q[j].w);
        s += (e[j].x + e[j].y) + (e[j].z + e[j].w);
    }
    #pragma unroll
    for (int o = 16; o > 0; o >>= 1) s += __shfl_xor_sync(0xffffffffu, s, o);

    float nonend = 1.f - ep;
    float scale = nonend / s;
    int off  = (cls == 1) ? 2 : (2 + FPN);
    int zoff = (cls == 1) ? (2 + FPN) : 2;
    float2* po = reinterpret_cast<float2*>(row + off);
    float2* pz = reinterpret_cast<float2*>(row + zoff);
    #pragma unroll
    for (int j = 0; j < 8; j++) {
        int cb = (lane + j * 32) * 2;   // float2 index
        __stcs(po + cb + 0, make_float2(e[j].x * scale, e[j].y * scale));
        __stcs(po + cb + 1, make_float2(e[j].z * scale, e[j].w * scale));
        __stcs(pz + cb + 0, make_float2(0.f, 0.f));
        __stcs(pz + cb + 1, make_float2(0.f, 0.f));
    }
    if (lane == 0) { row[0] = 0.f; row[1] = 0.f; }

    int idx = Y[n] - 2 - ((cls == 2) ? FPN : 0);
    idx = min(max(idx, 0), 1023);
    int g = idx >> 2;                    // float4 group
    if (lane == (g & 31)) {
        int j = g >> 5;
        float v = (idx & 2) ? ((idx & 1) ? q[j].w : q[j].z)
                            : ((idx & 1) ? q[j].y : q[j].x);
        out[n] = (v - logf(s)) + logf(nonend);
    }
}

extern "C" void kernel_launch(void* const* d_in, const int* in_sizes, int n_in,
                              void* d_out, int out_size)
{
    const float* X     = (const float*)d_in[0];
    const int*   pY    = (const int*)  d_in[1];
    const int*   Y     = (const int*)  d_in[2];
    const float* W_end = (const float*)d_in[3];
    const float* b_end = (const float*)d_in[4];
    const float* W_hcw = (const float*)d_in[5];
    const float* b_hcw = (const float*)d_in[6];
    const float* W_roo = (const float*)d_in[7];
    const float* b_roo = (const float*)d_in[8];
    float* out = (float*)d_out;

    cudaFuncSetAttribute(gemm_mma_kernel,
                         cudaFuncAttributeMaxDynamicSharedMemorySize, SM_TOTAL);

    prep_kernel<<<2048 + 4096, 256>>>(X, pY, W_end, b_end, W_hcw, W_roo, out);
    gemm_mma_kernel<<<304, 128, SM_TOTAL>>>(b_hcw, b_roo);   // persistent, 2 CTAs/SM
    finalize_kernel<<<NTOK / 8, 256>>>(pY, Y, out);
}